// round 8
// baseline (speedup 1.0000x reference)
#include <cuda_runtime.h>
#include <cuda_bf16.h>
#include <math.h>
#include <stdint.h>

#define SEQN 512
#define BATN 64
#define KIN  1024
#define HN   1024
#define STEP_ELEMS (BATN * HN)          // 65536 floats per timestep

// ---------------- static scratch (device globals; no allocs) ----------------
__device__ unsigned short g_xh[SEQN * BATN * KIN];   // bf16 hi of X
__device__ unsigned short g_xl[SEQN * BATN * KIN];   // bf16 lo of X
__device__ unsigned short g_wh[HN * KIN];            // bf16 hi of W_ih
__device__ unsigned short g_wl[HN * KIN];            // bf16 lo of W_ih

// Recurrence: bf16 hi/lo of current h (one timestep, rewritten every step)
__device__ unsigned short g_hh[STEP_ELEMS];
__device__ unsigned short g_hl[STEP_ELEMS];

// Recurrence split-K partial buffer: [8][BATN][HN] = 2 MB
#define NBLK 128
#define R_KSPL 8
#define R_K    128                      // k-range per block
#define R_NS   64                       // n-cols per block
#define RSTR   136                      // padded smem stride (K + 8)
__device__ float g_part[R_KSPL * BATN * HN];
__device__ volatile unsigned g_flags[NBLK * 32];
__device__ volatile unsigned g_sense;

// ---------------- warp-MMA helpers (plain sm_103-legal PTX) ----------------
__device__ __forceinline__ uint32_t smem_u32(const void* p) {
    uint32_t a;
    asm("{ .reg .u64 t; cvta.to.shared.u64 t, %1; cvt.u32.u64 %0, t; }"
        : "=r"(a) : "l"(p));
    return a;
}
__device__ __forceinline__ void ldm_x4(uint32_t* r, uint32_t addr) {
    asm volatile("ldmatrix.sync.aligned.m8n8.x4.shared.b16 {%0,%1,%2,%3}, [%4];"
                 : "=r"(r[0]), "=r"(r[1]), "=r"(r[2]), "=r"(r[3]) : "r"(addr));
}
__device__ __forceinline__ void mma_bf16(float* d, const uint32_t* a,
                                         uint32_t b0, uint32_t b1) {
    asm volatile("mma.sync.aligned.m16n8k16.row.col.f32.bf16.bf16.f32 "
                 "{%0,%1,%2,%3}, {%4,%5,%6,%7}, {%8,%9}, {%0,%1,%2,%3};"
                 : "+f"(d[0]), "+f"(d[1]), "+f"(d[2]), "+f"(d[3])
                 : "r"(a[0]), "r"(a[1]), "r"(a[2]), "r"(a[3]), "r"(b0), "r"(b1));
}

// ---------------------------------------------------------------------------
// fp32 -> (bf16 hi, bf16 lo) split helpers.
// ---------------------------------------------------------------------------
__device__ __forceinline__ void split4(float4 v, ushort4& h, ushort4& l) {
    __nv_bfloat16 hx = __float2bfloat16(v.x), hy = __float2bfloat16(v.y);
    __nv_bfloat16 hz = __float2bfloat16(v.z), hw = __float2bfloat16(v.w);
    h.x = __bfloat16_as_ushort(hx); h.y = __bfloat16_as_ushort(hy);
    h.z = __bfloat16_as_ushort(hz); h.w = __bfloat16_as_ushort(hw);
    l.x = __bfloat16_as_ushort(__float2bfloat16(v.x - __bfloat162float(hx)));
    l.y = __bfloat16_as_ushort(__float2bfloat16(v.y - __bfloat162float(hy)));
    l.z = __bfloat16_as_ushort(__float2bfloat16(v.z - __bfloat162float(hz)));
    l.w = __bfloat16_as_ushort(__float2bfloat16(v.w - __bfloat162float(hw)));
}
__global__ __launch_bounds__(256) void split_x_kernel(const float* __restrict__ X) {
    size_t i = (size_t)blockIdx.x * 256 + threadIdx.x;
    float4 v = ((const float4*)X)[i];
    ushort4 h, l;
    split4(v, h, l);
    ((ushort4*)g_xh)[i] = h;
    ((ushort4*)g_xl)[i] = l;
}
__global__ __launch_bounds__(256) void split_w_kernel(const float* __restrict__ W) {
    size_t i = (size_t)blockIdx.x * 256 + threadIdx.x;
    float4 v = ((const float4*)W)[i];
    ushort4 h, l;
    split4(v, h, l);
    ((ushort4*)g_wh)[i] = h;
    ((ushort4*)g_wl)[i] = l;
}

// ---------------------------------------------------------------------------
// Phase A via mma.sync bf16x3 (unchanged from round 6, PASSING).
// ---------------------------------------------------------------------------
#define TSTR 40
__global__ __launch_bounds__(256) void gemm_xproj_mma_kernel(
    const float* __restrict__ bih, const float* __restrict__ bhh,
    float* __restrict__ C)
{
    __shared__ __align__(16) unsigned short Ah[128][TSTR];
    __shared__ __align__(16) unsigned short Al[128][TSTR];
    __shared__ __align__(16) unsigned short Bh[128][TSTR];
    __shared__ __align__(16) unsigned short Bl[128][TSTR];
    __shared__ float bs[128];

    const int tid = threadIdx.x;
    const int wid = tid >> 5;
    const int lid = tid & 31;
    const int n0  = blockIdx.x * 128;
    const int m0  = blockIdx.y * 128;
    const int wm  = (wid >> 1) * 32;
    const int wn  = (wid & 1) * 64;

    if (tid < 128) bs[tid] = bih[n0 + tid] + bhh[n0 + tid];

    const int lr0 = tid >> 2;
    const int lc8 = (tid & 3) * 8;
    const int lrow = lid & 15;
    const int lcol = (lid >> 4) * 8;

    float acc[16][4];
#pragma unroll
    for (int t = 0; t < 16; t++)
#pragma unroll
        for (int e = 0; e < 4; e++) acc[t][e] = 0.0f;

    const uint32_t sAh = smem_u32(Ah), sAl = smem_u32(Al);
    const uint32_t sBh = smem_u32(Bh), sBl = smem_u32(Bl);

    for (int kc = 0; kc < KIN / 32; kc++) {
        if (kc) __syncthreads();
#pragma unroll
        for (int q = 0; q < 2; q++) {
            int row = lr0 + q * 64;
            size_t gx = (size_t)(m0 + row) * KIN + kc * 32 + lc8;
            size_t gw = (size_t)(n0 + row) * KIN + kc * 32 + lc8;
            *(uint4*)&Ah[row][lc8] = *(const uint4*)(g_xh + gx);
            *(uint4*)&Al[row][lc8] = *(const uint4*)(g_xl + gx);
            *(uint4*)&Bh[row][lc8] = *(const uint4*)(g_wh + gw);
            *(uint4*)&Bl[row][lc8] = *(const uint4*)(g_wl + gw);
        }
        __syncthreads();

#pragma unroll
        for (int ks = 0; ks < 2; ks++) {
            const int kb = ks * 16;
            uint32_t ah[2][4], al[2][4], bh[4][4], bl[4][4];
#pragma unroll
            for (int i = 0; i < 2; i++) {
                uint32_t off = (uint32_t)((wm + 16 * i + lrow) * TSTR + kb + lcol) * 2;
                ldm_x4(ah[i], sAh + off);
                ldm_x4(al[i], sAl + off);
            }
#pragma unroll
            for (int j4 = 0; j4 < 4; j4++) {
                uint32_t off = (uint32_t)((wn + 16 * j4 + lrow) * TSTR + kb + lcol) * 2;
                ldm_x4(bh[j4], sBh + off);
                ldm_x4(bl[j4], sBl + off);
            }
#pragma unroll
            for (int i = 0; i < 2; i++)
#pragma unroll
                for (int j = 0; j < 8; j++) {
                    int j4 = j >> 1, sub = j & 1;
                    float* d = acc[i * 8 + j];
                    mma_bf16(d, ah[i], bh[j4][sub], bh[j4][2 + sub]);
                    mma_bf16(d, ah[i], bl[j4][sub], bl[j4][2 + sub]);
                    mma_bf16(d, al[i], bh[j4][sub], bh[j4][2 + sub]);
                }
        }
    }

    const int er = lid >> 2;
    const int ec = (lid & 3) * 2;
#pragma unroll
    for (int i = 0; i < 2; i++)
#pragma unroll
        for (int j = 0; j < 8; j++) {
            const float* d = acc[i * 8 + j];
            int cl = wn + 8 * j + ec;
            int row = m0 + wm + 16 * i + er;
            float b0 = bs[cl], b1 = bs[cl + 1];
            float2 v0, v1;
            v0.x = d[0] + b0; v0.y = d[1] + b1;
            v1.x = d[2] + b0; v1.y = d[3] + b1;
            *(float2*)(C + (size_t)row * HN + n0 + cl) = v0;
            *(float2*)(C + (size_t)(row + 8) * HN + n0 + cl) = v1;
        }
}

// ---------------------------------------------------------------------------
// Flag-based sense-reversing grid barrier (unchanged).
// ---------------------------------------------------------------------------
__device__ __forceinline__ void gsync(unsigned& sense)
{
    const unsigned ns = sense ^ 1u;
    __syncthreads();
    if (blockIdx.x == 0) {
        if (threadIdx.x == 0) {
            __threadfence();
            g_flags[0] = ns;
        }
        if (threadIdx.x < NBLK) {
            while (g_flags[threadIdx.x * 32] != ns) { }
        }
        __syncthreads();
        if (threadIdx.x == 0) {
            __threadfence();
            g_sense = ns;
        }
        __syncthreads();
    } else {
        if (threadIdx.x == 0) {
            __threadfence();
            g_flags[blockIdx.x * 32] = ns;
            while (g_sense != ns) { }
            __threadfence();
        }
        __syncthreads();
    }
    sense = ns;
}

// ---------------------------------------------------------------------------
// Persistent recurrence kernel, HMMA bf16x3 step GEMM.
// 128 blocks = 16 N-splits x 8 K-splits; per block M=64, N=64, K=128.
// W_hh tile split to bf16 hi/lo in smem ONCE; h exchanged as bf16 hi/lo.
// Dynamic smem: Wh/Wl/Hh/Hl each [64][136] ushort = 68 KB total.
// ---------------------------------------------------------------------------
__global__ __launch_bounds__(256, 1) void rnn_recurrence_mma_kernel(
    const float* __restrict__ Whh, float* __restrict__ out)
{
    extern __shared__ __align__(16) unsigned short sm[];
    unsigned short* Wh = sm;
    unsigned short* Wl = sm + 64 * RSTR;
    unsigned short* Hh = sm + 2 * 64 * RSTR;
    unsigned short* Hl = sm + 3 * 64 * RSTR;

    const int tid = threadIdx.x;
    const int bid = blockIdx.x;
    const int ks  = bid & 7;            // 0..7   K-split
    const int ns  = bid >> 3;           // 0..15  N-split
    const int n0  = ns * R_NS;
    const int k0  = ks * R_K;
    unsigned sense = 0;

    // --- Prologue: split W_hh tile [n0..n0+64) x [k0..k0+128) to bf16 smem ---
#pragma unroll
    for (int it = 0; it < 8; it++) {
        int idx = it * 256 + tid;       // 0..2047 float4s
        int row = idx >> 5;             // 0..63 (n)
        int c4  = (idx & 31) * 4;       // 0..124 (k)
        float4 v = *(const float4*)(Whh + (size_t)(n0 + row) * KIN + k0 + c4);
        ushort4 h, l;
        split4(v, h, l);
        *(ushort4*)&Wh[row * RSTR + c4] = h;
        *(ushort4*)&Wl[row * RSTR + c4] = l;
    }

    // --- Step 0: h_0 = tanh(xp_0), also emit bf16 hi/lo ---
    if (tid < 128) {
        int fi = bid * 128 + tid;       // float4 index over 64x1024
        float4 v = ((const float4*)out)[fi];
        v.x = tanhf(v.x); v.y = tanhf(v.y); v.z = tanhf(v.z); v.w = tanhf(v.w);
        ((float4*)out)[fi] = v;
        ushort4 h, l;
        split4(v, h, l);
        ((ushort4*)g_hh)[fi] = h;
        ((ushort4*)g_hl)[fi] = l;
    }
    gsync(sense);                       // barrier #1

    const int wid  = tid >> 5;
    const int lid  = tid & 31;
    const int wm   = (wid >> 2) * 32;   // warp m offset (0, 32)
    const int wn   = (wid & 3) * 16;    // warp n offset (0,16,32,48)
    const int lrow = lid & 15;
    const int lcol = (lid >> 4) * 8;
    const int er   = lid >> 2;
    const int ec   = (lid & 3) * 2;
    const uint32_t sWh = smem_u32(Wh), sWl = smem_u32(Wl);
    const uint32_t sHh = smem_u32(Hh), sHl = smem_u32(Hl);
    float* pb = g_part + (size_t)ks * STEP_ELEMS;

    for (int s = 1; s < SEQN; s++) {
        float* outs = out + (size_t)s * STEP_ELEMS;

        // --- Stage h_{s-1} bf16 hi/lo slice [64 b][k0..k0+128) ---
#pragma unroll
        for (int it = 0; it < 4; it++) {
            int idx = it * 256 + tid;   // 0..1023 uint4s (8 bf16 each)
            int row = idx >> 4;         // 0..63
            int c8  = (idx & 15) * 8;   // 0..120
            *(uint4*)&Hh[row * RSTR + c8] =
                *(const uint4*)(g_hh + (size_t)row * HN + k0 + c8);
            *(uint4*)&Hl[row * RSTR + c8] =
                *(const uint4*)(g_hl + (size_t)row * HN + k0 + c8);
        }
        __syncthreads();

        // --- HMMA bf16x3: acc[2m][2n8] frags ---
        float acc[4][4];
#pragma unroll
        for (int t = 0; t < 4; t++)
#pragma unroll
            for (int e = 0; e < 4; e++) acc[t][e] = 0.0f;

#pragma unroll
        for (int k16 = 0; k16 < 8; k16++) {
            const int kk = k16 * 16;
            uint32_t ah[2][4], al[2][4], bh[4], bl[4];
#pragma unroll
            for (int i = 0; i < 2; i++) {
                uint32_t off = (uint32_t)((wm + 16 * i + lrow) * RSTR + kk + lcol) * 2;
                ldm_x4(ah[i], sHh + off);
                ldm_x4(al[i], sHl + off);
            }
            {
                uint32_t off = (uint32_t)((wn + lrow) * RSTR + kk + lcol) * 2;
                ldm_x4(bh, sWh + off);
                ldm_x4(bl, sWl + off);
            }
#pragma unroll
            for (int i = 0; i < 2; i++)
#pragma unroll
                for (int j = 0; j < 2; j++) {
                    float* d = acc[i * 2 + j];
                    mma_bf16(d, ah[i], bh[j], bh[2 + j]);   // hh
                    mma_bf16(d, ah[i], bl[j], bl[2 + j]);   // hl
                    mma_bf16(d, al[i], bh[j], bh[2 + j]);   // lh
                }
        }

        // --- Store partials to g_part[ks] ---
#pragma unroll
        for (int i = 0; i < 2; i++)
#pragma unroll
            for (int j = 0; j < 2; j++) {
                const float* d = acc[i * 2 + j];
                int row = wm + 16 * i + er;
                int cn  = n0 + wn + 8 * j + ec;
                float2 v0, v1;
                v0.x = d[0]; v0.y = d[1];
                v1.x = d[2]; v1.y = d[3];
                *(float2*)(pb + (size_t)row * HN + cn) = v0;
                *(float2*)(pb + (size_t)(row + 8) * HN + cn) = v1;
            }

        gsync(sense);                   // partials visible

        // --- Reduce 8 partials + xp, tanh, write h_s fp32 + bf16 hi/lo ---
        if (tid < 128) {
            int fi = bid * 128 + tid;
            float4 v = ((const float4*)outs)[fi];
#pragma unroll
            for (int kp = 0; kp < R_KSPL; kp++) {
                float4 p = ((const float4*)(g_part + (size_t)kp * STEP_ELEMS))[fi];
                v.x += p.x; v.y += p.y; v.z += p.z; v.w += p.w;
            }
            v.x = tanhf(v.x); v.y = tanhf(v.y);
            v.z = tanhf(v.z); v.w = tanhf(v.w);
            ((float4*)outs)[fi] = v;
            ushort4 h, l;
            split4(v, h, l);
            ((ushort4*)g_hh)[fi] = h;
            ((ushort4*)g_hl)[fi] = l;
        }

        // Skip final barrier: total barrier count 1 + 510*2 + 1 = 1022 (even),
        // so g_sense/g_flags return to 0 for the next graph replay.
        if (s != SEQN - 1) gsync(sense);
        else __syncthreads();
    }
}

// ---------------------------------------------------------------------------
extern "C" void kernel_launch(void* const* d_in, const int* in_sizes, int n_in,
                              void* d_out, int out_size)
{
    const float* X   = (const float*)d_in[0];   // [512, 64, 1024]
    const float* Wih = (const float*)d_in[1];   // [1024, 1024]
    const float* Whh = (const float*)d_in[2];   // [1024, 1024]
    const float* bih = (const float*)d_in[3];   // [1024]
    const float* bhh = (const float*)d_in[4];   // [1024]
    float* out = (float*)d_out;                 // [32768, 1024]

    const int rec_smem = 4 * 64 * RSTR * 2;     // 69632 bytes
    cudaFuncSetAttribute(rnn_recurrence_mma_kernel,
                         cudaFuncAttributeMaxDynamicSharedMemorySize, rec_smem);

    // Nodes 1-2: bf16 hi/lo splits of X and W_ih.
    split_x_kernel<<<(SEQN * BATN * KIN / 4) / 256, 256>>>(X);
    split_w_kernel<<<(HN * KIN / 4) / 256, 256>>>(Wih);

    // Node 3: x_proj via mma.sync bf16x3, biases fused, written into d_out.
    dim3 gA(HN / 128, (SEQN * BATN) / 128);     // (8, 256)
    gemm_xproj_mma_kernel<<<gA, 256>>>(bih, bhh, out);

    // Node 4: entire recurrence in one persistent kernel (HMMA step GEMM).
    rnn_recurrence_mma_kernel<<<NBLK, 256, rec_smem>>>(Whh, out);
}

// round 9
// speedup vs baseline: 1.0286x; 1.0286x over previous
#include <cuda_runtime.h>
#include <cuda_bf16.h>
#include <math.h>
#include <stdint.h>

#define SEQN 512
#define BATN 64
#define KIN  1024
#define HN   1024
#define STEP_ELEMS (BATN * HN)          // 65536 floats per timestep

// ---------------- static scratch (device globals; no allocs) ----------------
__device__ unsigned short g_xh[SEQN * BATN * KIN];   // bf16 hi of X
__device__ unsigned short g_xl[SEQN * BATN * KIN];   // bf16 lo of X
__device__ unsigned short g_wh[HN * KIN];            // bf16 hi of W_ih
__device__ unsigned short g_wl[HN * KIN];            // bf16 lo of W_ih

// Recurrence: bf16 hi/lo of current h (one timestep, rewritten every step)
__device__ unsigned short g_hh[STEP_ELEMS];
__device__ unsigned short g_hl[STEP_ELEMS];

// Recurrence split-K partial buffer: [8][BATN][HN] = 2 MB
#define NBLK 128
#define R_KSPL 8
#define R_K    128                      // k-range per block
#define R_NS   64                       // n-cols per block
#define RSTR   136                      // padded smem stride (K + 8)
__device__ float g_part[R_KSPL * BATN * HN];
__device__ volatile unsigned g_flags[NBLK * 32];
__device__ volatile unsigned g_sense;

// ---------------- warp-MMA helpers (plain sm_103-legal PTX) ----------------
__device__ __forceinline__ uint32_t smem_u32(const void* p) {
    uint32_t a;
    asm("{ .reg .u64 t; cvta.to.shared.u64 t, %1; cvt.u32.u64 %0, t; }"
        : "=r"(a) : "l"(p));
    return a;
}
__device__ __forceinline__ void ldm_x4(uint32_t* r, uint32_t addr) {
    asm volatile("ldmatrix.sync.aligned.m8n8.x4.shared.b16 {%0,%1,%2,%3}, [%4];"
                 : "=r"(r[0]), "=r"(r[1]), "=r"(r[2]), "=r"(r[3]) : "r"(addr));
}
__device__ __forceinline__ void mma_bf16(float* d, const uint32_t* a,
                                         uint32_t b0, uint32_t b1) {
    asm volatile("mma.sync.aligned.m16n8k16.row.col.f32.bf16.bf16.f32 "
                 "{%0,%1,%2,%3}, {%4,%5,%6,%7}, {%8,%9}, {%0,%1,%2,%3};"
                 : "+f"(d[0]), "+f"(d[1]), "+f"(d[2]), "+f"(d[3])
                 : "r"(a[0]), "r"(a[1]), "r"(a[2]), "r"(a[3]), "r"(b0), "r"(b1));
}

// ---------------------------------------------------------------------------
// fp32 -> (bf16 hi, bf16 lo) split helpers.
// ---------------------------------------------------------------------------
__device__ __forceinline__ void split4(float4 v, ushort4& h, ushort4& l) {
    __nv_bfloat16 hx = __float2bfloat16(v.x), hy = __float2bfloat16(v.y);
    __nv_bfloat16 hz = __float2bfloat16(v.z), hw = __float2bfloat16(v.w);
    h.x = __bfloat16_as_ushort(hx); h.y = __bfloat16_as_ushort(hy);
    h.z = __bfloat16_as_ushort(hz); h.w = __bfloat16_as_ushort(hw);
    l.x = __bfloat16_as_ushort(__float2bfloat16(v.x - __bfloat162float(hx)));
    l.y = __bfloat16_as_ushort(__float2bfloat16(v.y - __bfloat162float(hy)));
    l.z = __bfloat16_as_ushort(__float2bfloat16(v.z - __bfloat162float(hz)));
    l.w = __bfloat16_as_ushort(__float2bfloat16(v.w - __bfloat162float(hw)));
}
__global__ __launch_bounds__(256) void split_x_kernel(const float* __restrict__ X) {
    size_t i = (size_t)blockIdx.x * 256 + threadIdx.x;
    float4 v = ((const float4*)X)[i];
    ushort4 h, l;
    split4(v, h, l);
    ((ushort4*)g_xh)[i] = h;
    ((ushort4*)g_xl)[i] = l;
}
__global__ __launch_bounds__(256) void split_w_kernel(const float* __restrict__ W) {
    size_t i = (size_t)blockIdx.x * 256 + threadIdx.x;
    float4 v = ((const float4*)W)[i];
    ushort4 h, l;
    split4(v, h, l);
    ((ushort4*)g_wh)[i] = h;
    ((ushort4*)g_wl)[i] = l;
}

// ---------------------------------------------------------------------------
// Phase A via mma.sync bf16x3 (unchanged from round 6, PASSING).
// ---------------------------------------------------------------------------
#define TSTR 40
__global__ __launch_bounds__(256) void gemm_xproj_mma_kernel(
    const float* __restrict__ bih, const float* __restrict__ bhh,
    float* __restrict__ C)
{
    __shared__ __align__(16) unsigned short Ah[128][TSTR];
    __shared__ __align__(16) unsigned short Al[128][TSTR];
    __shared__ __align__(16) unsigned short Bh[128][TSTR];
    __shared__ __align__(16) unsigned short Bl[128][TSTR];
    __shared__ float bs[128];

    const int tid = threadIdx.x;
    const int wid = tid >> 5;
    const int lid = tid & 31;
    const int n0  = blockIdx.x * 128;
    const int m0  = blockIdx.y * 128;
    const int wm  = (wid >> 1) * 32;
    const int wn  = (wid & 1) * 64;

    if (tid < 128) bs[tid] = bih[n0 + tid] + bhh[n0 + tid];

    const int lr0 = tid >> 2;
    const int lc8 = (tid & 3) * 8;
    const int lrow = lid & 15;
    const int lcol = (lid >> 4) * 8;

    float acc[16][4];
#pragma unroll
    for (int t = 0; t < 16; t++)
#pragma unroll
        for (int e = 0; e < 4; e++) acc[t][e] = 0.0f;

    const uint32_t sAh = smem_u32(Ah), sAl = smem_u32(Al);
    const uint32_t sBh = smem_u32(Bh), sBl = smem_u32(Bl);

    for (int kc = 0; kc < KIN / 32; kc++) {
        if (kc) __syncthreads();
#pragma unroll
        for (int q = 0; q < 2; q++) {
            int row = lr0 + q * 64;
            size_t gx = (size_t)(m0 + row) * KIN + kc * 32 + lc8;
            size_t gw = (size_t)(n0 + row) * KIN + kc * 32 + lc8;
            *(uint4*)&Ah[row][lc8] = *(const uint4*)(g_xh + gx);
            *(uint4*)&Al[row][lc8] = *(const uint4*)(g_xl + gx);
            *(uint4*)&Bh[row][lc8] = *(const uint4*)(g_wh + gw);
            *(uint4*)&Bl[row][lc8] = *(const uint4*)(g_wl + gw);
        }
        __syncthreads();

#pragma unroll
        for (int ks = 0; ks < 2; ks++) {
            const int kb = ks * 16;
            uint32_t ah[2][4], al[2][4], bh[4][4], bl[4][4];
#pragma unroll
            for (int i = 0; i < 2; i++) {
                uint32_t off = (uint32_t)((wm + 16 * i + lrow) * TSTR + kb + lcol) * 2;
                ldm_x4(ah[i], sAh + off);
                ldm_x4(al[i], sAl + off);
            }
#pragma unroll
            for (int j4 = 0; j4 < 4; j4++) {
                uint32_t off = (uint32_t)((wn + 16 * j4 + lrow) * TSTR + kb + lcol) * 2;
                ldm_x4(bh[j4], sBh + off);
                ldm_x4(bl[j4], sBl + off);
            }
#pragma unroll
            for (int i = 0; i < 2; i++)
#pragma unroll
                for (int j = 0; j < 8; j++) {
                    int j4 = j >> 1, sub = j & 1;
                    float* d = acc[i * 8 + j];
                    mma_bf16(d, ah[i], bh[j4][sub], bh[j4][2 + sub]);
                    mma_bf16(d, ah[i], bl[j4][sub], bl[j4][2 + sub]);
                    mma_bf16(d, al[i], bh[j4][sub], bh[j4][2 + sub]);
                }
        }
    }

    const int er = lid >> 2;
    const int ec = (lid & 3) * 2;
#pragma unroll
    for (int i = 0; i < 2; i++)
#pragma unroll
        for (int j = 0; j < 8; j++) {
            const float* d = acc[i * 8 + j];
            int cl = wn + 8 * j + ec;
            int row = m0 + wm + 16 * i + er;
            float b0 = bs[cl], b1 = bs[cl + 1];
            float2 v0, v1;
            v0.x = d[0] + b0; v0.y = d[1] + b1;
            v1.x = d[2] + b0; v1.y = d[3] + b1;
            *(float2*)(C + (size_t)row * HN + n0 + cl) = v0;
            *(float2*)(C + (size_t)(row + 8) * HN + n0 + cl) = v1;
        }
}

// ---------------------------------------------------------------------------
// Flag-based sense-reversing grid barrier (unchanged).
// ---------------------------------------------------------------------------
__device__ __forceinline__ void gsync(unsigned& sense)
{
    const unsigned ns = sense ^ 1u;
    __syncthreads();
    if (blockIdx.x == 0) {
        if (threadIdx.x == 0) {
            __threadfence();
            g_flags[0] = ns;
        }
        if (threadIdx.x < NBLK) {
            while (g_flags[threadIdx.x * 32] != ns) { }
        }
        __syncthreads();
        if (threadIdx.x == 0) {
            __threadfence();
            g_sense = ns;
        }
        __syncthreads();
    } else {
        if (threadIdx.x == 0) {
            __threadfence();
            g_flags[blockIdx.x * 32] = ns;
            while (g_sense != ns) { }
            __threadfence();
        }
        __syncthreads();
    }
    sense = ns;
}

// ---------------------------------------------------------------------------
// Persistent recurrence kernel, HMMA bf16x3 step GEMM.
// 128 blocks = 16 N-splits x 8 K-splits; per block M=64, N=64, K=128.
// W_hh tile split to bf16 hi/lo in smem ONCE; h exchanged as bf16 hi/lo.
// Dynamic smem: Wh/Wl/Hh/Hl each [64][136] ushort = 68 KB total.
// ---------------------------------------------------------------------------
__global__ __launch_bounds__(256, 1) void rnn_recurrence_mma_kernel(
    const float* __restrict__ Whh, float* __restrict__ out)
{
    extern __shared__ __align__(16) unsigned short sm[];
    unsigned short* Wh = sm;
    unsigned short* Wl = sm + 64 * RSTR;
    unsigned short* Hh = sm + 2 * 64 * RSTR;
    unsigned short* Hl = sm + 3 * 64 * RSTR;

    const int tid = threadIdx.x;
    const int bid = blockIdx.x;
    const int ks  = bid & 7;            // 0..7   K-split
    const int ns  = bid >> 3;           // 0..15  N-split
    const int n0  = ns * R_NS;
    const int k0  = ks * R_K;
    unsigned sense = 0;

    // --- Prologue: split W_hh tile [n0..n0+64) x [k0..k0+128) to bf16 smem ---
#pragma unroll
    for (int it = 0; it < 8; it++) {
        int idx = it * 256 + tid;       // 0..2047 float4s
        int row = idx >> 5;             // 0..63 (n)
        int c4  = (idx & 31) * 4;       // 0..124 (k)
        float4 v = *(const float4*)(Whh + (size_t)(n0 + row) * KIN + k0 + c4);
        ushort4 h, l;
        split4(v, h, l);
        *(ushort4*)&Wh[row * RSTR + c4] = h;
        *(ushort4*)&Wl[row * RSTR + c4] = l;
    }

    // --- Step 0: h_0 = tanh(xp_0), also emit bf16 hi/lo ---
    if (tid < 128) {
        int fi = bid * 128 + tid;       // float4 index over 64x1024
        float4 v = ((const float4*)out)[fi];
        v.x = tanhf(v.x); v.y = tanhf(v.y); v.z = tanhf(v.z); v.w = tanhf(v.w);
        ((float4*)out)[fi] = v;
        ushort4 h, l;
        split4(v, h, l);
        ((ushort4*)g_hh)[fi] = h;
        ((ushort4*)g_hl)[fi] = l;
    }
    gsync(sense);                       // barrier #1

    const int wid  = tid >> 5;
    const int lid  = tid & 31;
    const int wm   = (wid >> 2) * 32;   // warp m offset (0, 32)
    const int wn   = (wid & 3) * 16;    // warp n offset (0,16,32,48)
    const int lrow = lid & 15;
    const int lcol = (lid >> 4) * 8;
    const int er   = lid >> 2;
    const int ec   = (lid & 3) * 2;
    const uint32_t sWh = smem_u32(Wh), sWl = smem_u32(Wl);
    const uint32_t sHh = smem_u32(Hh), sHl = smem_u32(Hl);
    float* pb = g_part + (size_t)ks * STEP_ELEMS;

    for (int s = 1; s < SEQN; s++) {
        float* outs = out + (size_t)s * STEP_ELEMS;

        // --- Stage h_{s-1} bf16 hi/lo slice [64 b][k0..k0+128) ---
#pragma unroll
        for (int it = 0; it < 4; it++) {
            int idx = it * 256 + tid;   // 0..1023 uint4s (8 bf16 each)
            int row = idx >> 4;         // 0..63
            int c8  = (idx & 15) * 8;   // 0..120
            *(uint4*)&Hh[row * RSTR + c8] =
                *(const uint4*)(g_hh + (size_t)row * HN + k0 + c8);
            *(uint4*)&Hl[row * RSTR + c8] =
                *(const uint4*)(g_hl + (size_t)row * HN + k0 + c8);
        }
        __syncthreads();

        // --- HMMA bf16x3: acc[2m][2n8] frags ---
        float acc[4][4];
#pragma unroll
        for (int t = 0; t < 4; t++)
#pragma unroll
            for (int e = 0; e < 4; e++) acc[t][e] = 0.0f;

#pragma unroll
        for (int k16 = 0; k16 < 8; k16++) {
            const int kk = k16 * 16;
            uint32_t ah[2][4], al[2][4], bh[4], bl[4];
#pragma unroll
            for (int i = 0; i < 2; i++) {
                uint32_t off = (uint32_t)((wm + 16 * i + lrow) * RSTR + kk + lcol) * 2;
                ldm_x4(ah[i], sHh + off);
                ldm_x4(al[i], sHl + off);
            }
            {
                uint32_t off = (uint32_t)((wn + lrow) * RSTR + kk + lcol) * 2;
                ldm_x4(bh, sWh + off);
                ldm_x4(bl, sWl + off);
            }
#pragma unroll
            for (int i = 0; i < 2; i++)
#pragma unroll
                for (int j = 0; j < 2; j++) {
                    float* d = acc[i * 2 + j];
                    mma_bf16(d, ah[i], bh[j], bh[2 + j]);   // hh
                    mma_bf16(d, ah[i], bl[j], bl[2 + j]);   // hl
                    mma_bf16(d, al[i], bh[j], bh[2 + j]);   // lh
                }
        }

        // --- Store partials to g_part[ks] ---
#pragma unroll
        for (int i = 0; i < 2; i++)
#pragma unroll
            for (int j = 0; j < 2; j++) {
                const float* d = acc[i * 2 + j];
                int row = wm + 16 * i + er;
                int cn  = n0 + wn + 8 * j + ec;
                float2 v0, v1;
                v0.x = d[0]; v0.y = d[1];
                v1.x = d[2]; v1.y = d[3];
                *(float2*)(pb + (size_t)row * HN + cn) = v0;
                *(float2*)(pb + (size_t)(row + 8) * HN + cn) = v1;
            }

        gsync(sense);                   // partials visible

        // --- Reduce 8 partials + xp, tanh, write h_s fp32 + bf16 hi/lo ---
        if (tid < 128) {
            int fi = bid * 128 + tid;
            float4 v = ((const float4*)outs)[fi];
#pragma unroll
            for (int kp = 0; kp < R_KSPL; kp++) {
                float4 p = ((const float4*)(g_part + (size_t)kp * STEP_ELEMS))[fi];
                v.x += p.x; v.y += p.y; v.z += p.z; v.w += p.w;
            }
            v.x = tanhf(v.x); v.y = tanhf(v.y);
            v.z = tanhf(v.z); v.w = tanhf(v.w);
            ((float4*)outs)[fi] = v;
            ushort4 h, l;
            split4(v, h, l);
            ((ushort4*)g_hh)[fi] = h;
            ((ushort4*)g_hl)[fi] = l;
        }

        // Skip final barrier: total barrier count 1 + 510*2 + 1 = 1022 (even),
        // so g_sense/g_flags return to 0 for the next graph replay.
        if (s != SEQN - 1) gsync(sense);
        else __syncthreads();
    }
}

// ---------------------------------------------------------------------------
extern "C" void kernel_launch(void* const* d_in, const int* in_sizes, int n_in,
                              void* d_out, int out_size)
{
    const float* X   = (const float*)d_in[0];   // [512, 64, 1024]
    const float* Wih = (const float*)d_in[1];   // [1024, 1024]
    const float* Whh = (const float*)d_in[2];   // [1024, 1024]
    const float* bih = (const float*)d_in[3];   // [1024]
    const float* bhh = (const float*)d_in[4];   // [1024]
    float* out = (float*)d_out;                 // [32768, 1024]

    const int rec_smem = 4 * 64 * RSTR * 2;     // 69632 bytes
    cudaFuncSetAttribute(rnn_recurrence_mma_kernel,
                         cudaFuncAttributeMaxDynamicSharedMemorySize, rec_smem);

    // Nodes 1-2: bf16 hi/lo splits of X and W_ih.
    split_x_kernel<<<(SEQN * BATN * KIN / 4) / 256, 256>>>(X);
    split_w_kernel<<<(HN * KIN / 4) / 256, 256>>>(Wih);

    // Node 3: x_proj via mma.sync bf16x3, biases fused, written into d_out.
    dim3 gA(HN / 128, (SEQN * BATN) / 128);     // (8, 256)
    gemm_xproj_mma_kernel<<<gA, 256>>>(bih, bhh, out);

    // Node 4: entire recurrence in one persistent kernel (HMMA step GEMM).
    rnn_recurrence_mma_kernel<<<NBLK, 256, rec_smem>>>(Whh, out);
}